// round 2
// baseline (speedup 1.0000x reference)
#include <cuda_runtime.h>
#include <cstdint>
#include <cstddef>

#define D        8
#define HIDDEN   64
#define WIDTH    128
#define NTOT     65536
#define PAIRS    (NTOT / 2)
#define TSTEPS   8
#define NSUB     4
#define NSEG     7
#define NSTAGE   84          // 7 segs * 4 substeps * 3 stage-times
#define ROWU2    9           // ulonglong2 (16B) per param row: 8 W-pairs + 8 U-pairs + {B,B} + {WU,WU}
#define NCTA     148
#define PPC      222         // ceil(PAIRS / NCTA)

typedef unsigned long long u64;

// Per-stage parameter rows, duplicated for f32x2 consumption.
// Layout per row k: [w0w0 w1w1 ... w7w7 | u0u0 ... u7u7 | B B WU WU]
__device__ float4 gParams[NSTAGE * WIDTH * ROWU2];   // 1.548 MB static device scratch

// ---------------- f32x2 helpers ----------------
__device__ __forceinline__ u64 pack2(float x, float y) {
    u64 r; asm("mov.b64 %0, {%1, %2};" : "=l"(r) : "f"(x), "f"(y)); return r;
}
__device__ __forceinline__ void unpack2(u64 v, float& x, float& y) {
    asm("mov.b64 {%0, %1}, %2;" : "=f"(x), "=f"(y) : "l"(v));
}
__device__ __forceinline__ u64 fma2(u64 a, u64 b, u64 c) {
    u64 d; asm("fma.rn.f32x2 %0, %1, %2, %3;" : "=l"(d) : "l"(a), "l"(b), "l"(c)); return d;
}
__device__ __forceinline__ u64 add2(u64 a, u64 b) {
    u64 d; asm("add.rn.f32x2 %0, %1, %2;" : "=l"(d) : "l"(a), "l"(b)); return d;
}
__device__ __forceinline__ u64 mul2(u64 a, u64 b) {
    u64 d; asm("mul.rn.f32x2 %0, %1, %2;" : "=l"(d) : "l"(a), "l"(b)); return d;
}
__device__ __forceinline__ float tanh_fast(float x) {
    float y; asm("tanh.approx.f32 %0, %1;" : "=f"(y) : "f"(x)); return y;
}
__device__ __forceinline__ u64 tanh2(u64 v) {
    float x, y; unpack2(v, x, y);
    return pack2(tanh_fast(x), tanh_fast(y));
}

// ---------------- cp.async helpers ----------------
__device__ __forceinline__ void cp16(void* dst_smem, const void* src) {
    uint32_t d = (uint32_t)__cvta_generic_to_shared(dst_smem);
    asm volatile("cp.async.cg.shared.global [%0], [%1], 16;" :: "r"(d), "l"(src));
}
__device__ __forceinline__ void cp_commit() {
    asm volatile("cp.async.commit_group;");
}
__device__ __forceinline__ void cp_wait1() {
    asm volatile("cp.async.wait_group 1;");
}

// ---------------- Kernel A: hypernetwork for all 84 stage times ----------------
__global__ void __launch_bounds__(128) hyper_kernel(
    const float* __restrict__ ts,
    const float* __restrict__ w1, const float* __restrict__ b1,
    const float* __restrict__ w2, const float* __restrict__ b2,
    const float* __restrict__ w3, const float* __restrict__ b3)
{
    const int s   = blockIdx.x;          // 0..83
    const int seg = s / 12;
    const int sub = (s % 12) / 3;
    const int st  = s % 3;

    const float t0 = ts[seg];
    const float t1 = ts[seg + 1];
    const float dt = (t1 - t0) * (1.0f / NSUB);
    const float t  = t0 + sub * dt + (st == 0 ? 0.0f : (st == 1 ? 0.5f * dt : dt));

    __shared__ float h1[HIDDEN];
    __shared__ float h2[HIDDEN];
    __shared__ float p[3 * WIDTH * D + WIDTH];   // 3200 floats

    const int tid = threadIdx.x;

    if (tid < HIDDEN)
        h1[tid] = tanhf(w1[tid] * t + b1[tid]);
    __syncthreads();

    if (tid < HIDDEN) {
        float acc = b2[tid];
        const float* wr = w2 + tid * HIDDEN;
        #pragma unroll 8
        for (int j = 0; j < HIDDEN; j++) acc += wr[j] * h1[j];
        h2[tid] = tanhf(acc);
    }
    __syncthreads();

    for (int r = tid; r < 3 * WIDTH * D + WIDTH; r += blockDim.x) {
        float acc = b3[r];
        const float* wr = w3 + (size_t)r * HIDDEN;
        #pragma unroll 8
        for (int j = 0; j < HIDDEN; j++) acc += wr[j] * h2[j];
        p[r] = acc;
    }
    __syncthreads();

    if (tid < WIDTH) {
        const int k = tid;
        float* out = (float*)gParams + ((size_t)s * WIDTH + k) * (ROWU2 * 4);
        const float B = p[3 * WIDTH * D + k];
        float wu = 0.0f;
        #pragma unroll
        for (int j = 0; j < D; j++) {
            const float W  = p[k * D + j];
            const float Ur = p[WIDTH * D + k * D + j];
            const float G  = p[2 * WIDTH * D + k * D + j];
            const float U  = Ur * (1.0f / (1.0f + __expf(-G)));
            wu += W * U;
            out[2 * j]          = W;  out[2 * j + 1]      = W;
            out[16 + 2 * j]     = U;  out[16 + 2 * j + 1] = U;
        }
        out[32] = B;  out[33] = B;
        out[34] = wu; out[35] = wu;
    }
}

// ---------------- Kernel B: RK4 integration, 2 samples/thread via f32x2 ----------------

__device__ __forceinline__ void prefetch_stage(ulonglong2* sp, const ulonglong2* __restrict__ src, int tid)
{
    #pragma unroll 1
    for (int i = tid; i < WIDTH * ROWU2; i += 256)
        cp16(sp + i, src + i);
    cp_commit();
}

__device__ __forceinline__ void rhs_eval(const u64 zs[D], u64 dz[D], u64& dl,
                                         const ulonglong2* __restrict__ sp)
{
    const u64 NEG1 = pack2(-1.0f, -1.0f);
    u64 tr = 0ULL;
    #pragma unroll
    for (int j = 0; j < D; j++) dz[j] = 0ULL;

    #pragma unroll 2
    for (int k = 0; k < WIDTH; k++) {
        const ulonglong2* rp = sp + k * ROWU2;
        const ulonglong2 q0 = rp[0];   // w0 w1
        const ulonglong2 q1 = rp[1];   // w2 w3
        const ulonglong2 q2 = rp[2];   // w4 w5
        const ulonglong2 q3 = rp[3];   // w6 w7
        const ulonglong2 qb = rp[8];   // B  WU

        u64 s0 = fma2(q0.x, zs[0], qb.x);
        u64 s1 = mul2(q0.y, zs[1]);
        s0 = fma2(q1.x, zs[2], s0);
        s1 = fma2(q1.y, zs[3], s1);
        s0 = fma2(q2.x, zs[4], s0);
        s1 = fma2(q2.y, zs[5], s1);
        s0 = fma2(q3.x, zs[6], s0);
        s1 = fma2(q3.y, zs[7], s1);

        const u64 h = tanh2(add2(s0, s1));

        const ulonglong2 u0 = rp[4];
        const ulonglong2 u1 = rp[5];
        const ulonglong2 u2 = rp[6];
        const ulonglong2 u3 = rp[7];
        dz[0] = fma2(h, u0.x, dz[0]);
        dz[1] = fma2(h, u0.y, dz[1]);
        dz[2] = fma2(h, u1.x, dz[2]);
        dz[3] = fma2(h, u1.y, dz[3]);
        dz[4] = fma2(h, u2.x, dz[4]);
        dz[5] = fma2(h, u2.y, dz[5]);
        dz[6] = fma2(h, u3.x, dz[6]);
        dz[7] = fma2(h, u3.y, dz[7]);

        const u64 hm = fma2(h, h, NEG1);   // h^2 - 1 = -(1 - h^2)
        tr = fma2(hm, qb.y, tr);           // accumulates -sum (1-h^2) WU
    }

    const u64 invw = pack2(1.0f / WIDTH, 1.0f / WIDTH);
    #pragma unroll
    for (int j = 0; j < D; j++) dz[j] = mul2(dz[j], invw);
    dl = mul2(tr, invw);                   // rhs_logp = -trace
}

__device__ __forceinline__ void store_state(float* __restrict__ out, int t, int n0,
                                            const u64 z[D], u64 lp)
{
    float a[D], b[D];
    #pragma unroll
    for (int j = 0; j < D; j++) unpack2(z[j], a[j], b[j]);
    float4* pz = (float4*)(out + (size_t)t * NTOT * D + (size_t)n0 * D);
    pz[0] = make_float4(a[0], a[1], a[2], a[3]);
    pz[1] = make_float4(a[4], a[5], a[6], a[7]);
    pz[2] = make_float4(b[0], b[1], b[2], b[3]);
    pz[3] = make_float4(b[4], b[5], b[6], b[7]);
    float la, lb; unpack2(lp, la, lb);
    float2* pl = (float2*)(out + (size_t)TSTEPS * NTOT * D + (size_t)t * NTOT + n0);
    *pl = make_float2(la, lb);
}

__global__ void __launch_bounds__(256, 1) cnf_kernel(
    const float* __restrict__ ts,
    const float* __restrict__ z0,
    const float* __restrict__ lp0,
    float* __restrict__ out)
{
    __shared__ ulonglong2 spbuf[2][WIDTH * ROWU2];    // 2 x 18432 B

    const int tid  = threadIdx.x;
    const int pair = blockIdx.x * PPC + tid;          // contiguous chunk per CTA
    const bool valid = (tid < PPC) && (pair < PAIRS);
    const int n0   = pair * 2;

    const ulonglong2* gp = (const ulonglong2*)gParams;

    // kick off prefetch of stage 0 into buffer 0 ASAP
    ulonglong2* bufA = spbuf[0];
    ulonglong2* bufB = spbuf[1];
    prefetch_stage(bufA, gp, tid);

    u64 z[D] = {0,0,0,0,0,0,0,0}, lp = 0ULL;
    if (valid) {
        const float4* pa = (const float4*)(z0 + (size_t)n0 * D);
        const float4 a0 = pa[0], a1 = pa[1], b0 = pa[2], b1 = pa[3];
        z[0] = pack2(a0.x, b0.x); z[1] = pack2(a0.y, b0.y);
        z[2] = pack2(a0.z, b0.z); z[3] = pack2(a0.w, b0.w);
        z[4] = pack2(a1.x, b1.x); z[5] = pack2(a1.y, b1.y);
        z[6] = pack2(a1.z, b1.z); z[7] = pack2(a1.w, b1.w);
        const float2 l = *(const float2*)(lp0 + n0);
        lp = pack2(l.x, l.y);

        // t = ts[0] snapshot
        store_state(out, 0, n0, z, lp);
    }

    for (int seg = 0; seg < NSEG; seg++) {
        const float dt  = (ts[seg + 1] - ts[seg]) * (1.0f / NSUB);
        const u64 dth = pack2(0.5f * dt, 0.5f * dt);
        const u64 dtf = pack2(dt, dt);
        const u64 dt6 = pack2(dt * (1.0f / 6.0f), dt * (1.0f / 6.0f));
        const u64 two = pack2(2.0f, 2.0f);

        for (int sub = 0; sub < NSUB; sub++) {
            const int sb = (seg * NSUB + sub) * 3;
            u64 acc[D], lacc, zs[D], dz[D], dl;

            // invariant: bufA has stage sb in flight (or landed)
            prefetch_stage(bufB, gp + (size_t)(sb + 1) * WIDTH * ROWU2, tid);
            cp_wait1();            // bufA landed (bufB may still fly)
            __syncthreads();

            // k1 @ t  (bufA = sb)
            if (valid) {
                rhs_eval(z, dz, dl, bufA);
                #pragma unroll
                for (int j = 0; j < D; j++) { acc[j] = dz[j]; zs[j] = fma2(dth, dz[j], z[j]); }
                lacc = dl;
            }
            __syncthreads();       // readers done with bufA
            prefetch_stage(bufA, gp + (size_t)(sb + 2) * WIDTH * ROWU2, tid);
            cp_wait1();            // bufB landed
            __syncthreads();

            // k2, k3 @ t + dt/2  (bufB = sb+1, same params both stages)
            if (valid) {
                rhs_eval(zs, dz, dl, bufB);
                #pragma unroll
                for (int j = 0; j < D; j++) { acc[j] = fma2(two, dz[j], acc[j]); zs[j] = fma2(dth, dz[j], z[j]); }
                lacc = fma2(two, dl, lacc);

                rhs_eval(zs, dz, dl, bufB);
                #pragma unroll
                for (int j = 0; j < D; j++) { acc[j] = fma2(two, dz[j], acc[j]); zs[j] = fma2(dtf, dz[j], z[j]); }
                lacc = fma2(two, dl, lacc);
            }
            __syncthreads();       // readers done with bufB
            {
                int nxt = sb + 3; if (nxt >= NSTAGE) nxt = 0;   // harmless dummy on last substep
                prefetch_stage(bufB, gp + (size_t)nxt * WIDTH * ROWU2, tid);
            }
            cp_wait1();            // bufA landed
            __syncthreads();

            // k4 @ t + dt  (bufA = sb+2)
            if (valid) {
                rhs_eval(zs, dz, dl, bufA);
                #pragma unroll
                for (int j = 0; j < D; j++) { acc[j] = add2(acc[j], dz[j]); z[j] = fma2(dt6, acc[j], z[j]); }
                lacc = add2(lacc, dl);
                lp = fma2(dt6, lacc, lp);
            }
            __syncthreads();       // k4 readers done before next-iter prefetch reuses bufA slot

            // swap: bufB now holds next substep's first stage
            ulonglong2* tmp = bufA; bufA = bufB; bufB = tmp;
        }
        if (valid) store_state(out, seg + 1, n0, z, lp);
    }
}

// ---------------- launch ----------------
extern "C" void kernel_launch(void* const* d_in, const int* in_sizes, int n_in,
                              void* d_out, int out_size)
{
    const float* ts  = (const float*)d_in[0];
    const float* z0  = (const float*)d_in[1];
    const float* lp0 = (const float*)d_in[2];
    const float* w1  = (const float*)d_in[3];
    const float* b1  = (const float*)d_in[4];
    const float* w2  = (const float*)d_in[5];
    const float* b2  = (const float*)d_in[6];
    const float* w3  = (const float*)d_in[7];
    const float* b3  = (const float*)d_in[8];

    hyper_kernel<<<NSTAGE, 128>>>(ts, w1, b1, w2, b2, w3, b3);
    cnf_kernel<<<NCTA, 256>>>(ts, z0, lp0, (float*)d_out);
}